// round 2
// baseline (speedup 1.0000x reference)
#include <cuda_runtime.h>
#include <cuda_bf16.h>
#include <math.h>

// Shapes
#define B_SZ 4096
#define P_SZ 256
#define F_SZ 20
#define H_SZ 18
#define W_SZ 18
#define HW   (H_SZ * W_SZ)          // 324
#define FHW  (F_SZ * HW)            // 6480
#define PI_C 3.14159f

// Scratch (no allocations allowed; use device globals)
__device__ float g_h[B_SZ * P_SZ];          // relu(pc @ W1 + b1)
__device__ float g_aff[B_SZ * F_SZ * 4];    // per (b,f): u, v, Bx, By

// ---------------------------------------------------------------------------
// Kernel 1: h = relu(pc @ W1 + b1).  M=4096, N=256, K=256.
// Register-blocked SGEMM: BM=128, BN=64, BK=16, per-thread 8x4, 256 threads.
// ---------------------------------------------------------------------------
__global__ void __launch_bounds__(256) gemm_relu_kernel(
    const float* __restrict__ A,      // (4096, 256)
    const float* __restrict__ W,      // (256, 256)
    const float* __restrict__ bias)   // (256)
{
    const int BM = 128, BN = 64, BK = 16;
    __shared__ float As[BK][BM + 4];  // [k][m], padded vs. store conflicts
    __shared__ float Bs[BK][BN];      // [k][n]

    int tid = threadIdx.x;
    int tx = tid & 15;      // 0..15 -> cols
    int ty = tid >> 4;      // 0..15 -> rows
    int row0 = blockIdx.x * BM;
    int col0 = blockIdx.y * BN;

    float acc[8][4];
#pragma unroll
    for (int i = 0; i < 8; i++)
#pragma unroll
        for (int j = 0; j < 4; j++) acc[i][j] = 0.f;

    for (int k0 = 0; k0 < P_SZ; k0 += BK) {
        // A tile: 128x16 -> transposed into As[k][m]; 512 float4, 2/thread
#pragma unroll
        for (int l = 0; l < 2; l++) {
            int idx = tid + l * 256;          // 0..511
            int m   = idx >> 2;               // 0..127
            int kq  = (idx & 3) << 2;         // 0,4,8,12
            float4 v = *(const float4*)&A[(row0 + m) * P_SZ + k0 + kq];
            As[kq + 0][m] = v.x;
            As[kq + 1][m] = v.y;
            As[kq + 2][m] = v.z;
            As[kq + 3][m] = v.w;
        }
        // B tile: 16x64 -> Bs[k][n]; 256 float4, 1/thread
        {
            int k = tid >> 4;                 // 0..15
            int n = (tid & 15) << 2;          // 0..60
            *(float4*)&Bs[k][n] = *(const float4*)&W[(k0 + k) * P_SZ + col0 + n];
        }
        __syncthreads();

#pragma unroll
        for (int k = 0; k < BK; k++) {
            float4 a0 = *(const float4*)&As[k][ty * 8];
            float4 a1 = *(const float4*)&As[k][ty * 8 + 4];
            float4 bv = *(const float4*)&Bs[k][tx * 4];
            float a[8] = {a0.x, a0.y, a0.z, a0.w, a1.x, a1.y, a1.z, a1.w};
            float bb[4] = {bv.x, bv.y, bv.z, bv.w};
#pragma unroll
            for (int i = 0; i < 8; i++)
#pragma unroll
                for (int j = 0; j < 4; j++)
                    acc[i][j] = fmaf(a[i], bb[j], acc[i][j]);
        }
        __syncthreads();
    }

    // Epilogue: + bias, relu, store
#pragma unroll
    for (int i = 0; i < 8; i++) {
        int r = row0 + ty * 8 + i;
#pragma unroll
        for (int j = 0; j < 4; j++) {
            int c = col0 + tx * 4 + j;
            float v = acc[i][j] + bias[c];
            g_h[r * P_SZ + c] = fmaxf(v, 0.f);
        }
    }
}

// ---------------------------------------------------------------------------
// Kernel 2: per (b,f) affine coefficients.
// raw = h @ [Ws | Wr | Wt] + [bs | br | bt]   (4096 x 80), then activations:
//   scale = 2*sigmoid(raw[f]); angle = tanh(raw[20+f])*PI;
//   tx = tanh(raw[40+2f]); ty = tanh(raw[41+2f])
//   u = 9*scale*cos(angle); v = 9*scale*sin(angle); Bx = 9*tx+8.5; By = 9*ty+8.5
// 16 batch rows per block, 256 threads.
// ---------------------------------------------------------------------------
__global__ void __launch_bounds__(256) params_kernel(
    const float* __restrict__ Ws, const float* __restrict__ bs,
    const float* __restrict__ Wr, const float* __restrict__ br,
    const float* __restrict__ Wt, const float* __restrict__ bt)
{
    __shared__ float hs[16][P_SZ + 4];
    __shared__ float raw[16][80];
    int tid = threadIdx.x;
    int b0 = blockIdx.x * 16;

    for (int i = tid; i < 16 * P_SZ; i += 256)
        hs[i >> 8][i & 255] = g_h[(b0 + (i >> 8)) * P_SZ + (i & 255)];
    __syncthreads();

    for (int o = tid; o < 16 * 80; o += 256) {
        int bi = o / 80, j = o - bi * 80;
        const float* wcol;
        int stride;
        float acc;
        if (j < 20)       { wcol = Ws + j;        stride = 20; acc = bs[j]; }
        else if (j < 40)  { wcol = Wr + (j - 20); stride = 20; acc = br[j - 20]; }
        else              { wcol = Wt + (j - 40); stride = 40; acc = bt[j - 40]; }
#pragma unroll 8
        for (int k = 0; k < P_SZ; k++)
            acc = fmaf(hs[bi][k], wcol[k * stride], acc);
        raw[bi][j] = acc;
    }
    __syncthreads();

    for (int o = tid; o < 16 * F_SZ; o += 256) {
        int bi = o / F_SZ, f = o - bi * F_SZ;
        float scale = 2.f / (1.f + expf(-raw[bi][f]));
        float angle = tanhf(raw[bi][20 + f]) * PI_C;
        float tx = tanhf(raw[bi][40 + 2 * f]);
        float ty = tanhf(raw[bi][41 + 2 * f]);
        float s, c;
        sincosf(angle, &s, &c);
        float4 r = make_float4(9.f * scale * c,
                               9.f * scale * s,
                               9.f * tx + 8.5f,
                               9.f * ty + 8.5f);
        *(float4*)&g_aff[(b0 + bi) * 80 + f * 4] = r;
    }
}

// ---------------------------------------------------------------------------
// Kernel 3: trilinear sampling. One CTA per batch b; full 20x18x18 volume in
// SMEM (25.9 KB). Each output pixel = 8-tap gather with zero padding.
// ---------------------------------------------------------------------------
__global__ void __launch_bounds__(256) sample_kernel(
    const float* __restrict__ fmap,   // (B, 20, 18, 18)
    float* __restrict__ out)          // (B, 20, 18, 18)
{
    __shared__ float vol[FHW];
    __shared__ float4 affs[F_SZ];
    int b = blockIdx.x;
    int tid = threadIdx.x;

    const float4* fb4 = (const float4*)(fmap + b * FHW);
    float4* vol4 = (float4*)vol;
    for (int i = tid; i < FHW / 4; i += 256) vol4[i] = fb4[i];  // 6480 % 4 == 0
    if (tid < F_SZ) affs[tid] = *(const float4*)&g_aff[b * 80 + tid * 4];
    __syncthreads();

    float* ob = out + b * FHW;
    for (int idx = tid; idx < FHW; idx += 256) {
        int f = idx / HW;
        int p = idx - f * HW;
        int y = p / W_SZ;
        int x = p - y * W_SZ;

        float gx = (2.f * x) / 17.f - 1.f;
        float gy = (2.f * y) / 17.f - 1.f;
        float4 A = affs[f];
        float ix = A.x * gx - A.y * gy + A.z;
        float iy = A.y * gx + A.x * gy + A.w;
        float iz = f * (20.f / 19.f) - 0.5f;

        float x0f = floorf(ix), y0f = floorf(iy), z0f = floorf(iz);
        float wx = ix - x0f, wy = iy - y0f, wz = iz - z0f;
        int x0 = (int)x0f, y0 = (int)y0f, z0 = (int)z0f;

        float acc = 0.f;
#pragma unroll
        for (int cz = 0; cz < 2; cz++) {
            int z = z0 + cz;
            if ((unsigned)z >= (unsigned)F_SZ) continue;
            float wzz = cz ? wz : 1.f - wz;
            float bil = 0.f;
#pragma unroll
            for (int cy = 0; cy < 2; cy++) {
                int yy = y0 + cy;
                if ((unsigned)yy >= (unsigned)H_SZ) continue;
                float wyy = cy ? wy : 1.f - wy;
#pragma unroll
                for (int cx = 0; cx < 2; cx++) {
                    int xx = x0 + cx;
                    if ((unsigned)xx >= (unsigned)W_SZ) continue;
                    float wxx = cx ? wx : 1.f - wx;
                    bil = fmaf(wxx * wyy, vol[z * HW + yy * W_SZ + xx], bil);
                }
            }
            acc = fmaf(wzz, bil, acc);
        }
        ob[idx] = acc;
    }
}

// ---------------------------------------------------------------------------
extern "C" void kernel_launch(void* const* d_in, const int* in_sizes, int n_in,
                              void* d_out, int out_size)
{
    const float* fmap = (const float*)d_in[0];  // (4096, 20, 18, 18)
    const float* pc   = (const float*)d_in[1];  // (4096, 256)
    const float* W1   = (const float*)d_in[2];  // (256, 256)
    const float* b1   = (const float*)d_in[3];  // (256)
    const float* Ws   = (const float*)d_in[4];  // (256, 20)
    const float* bs   = (const float*)d_in[5];  // (20)
    const float* Wr   = (const float*)d_in[6];  // (256, 20)
    const float* br   = (const float*)d_in[7];  // (20)
    const float* Wt   = (const float*)d_in[8];  // (256, 40)
    const float* bt   = (const float*)d_in[9];  // (40)
    float* out = (float*)d_out;

    gemm_relu_kernel<<<dim3(B_SZ / 128, P_SZ / 64), 256>>>(pc, W1, b1);
    params_kernel<<<B_SZ / 16, 256>>>(Ws, bs, Wr, br, Wt, bt);
    sample_kernel<<<B_SZ, 256>>>(fmap, out);
}

// round 4
// speedup vs baseline: 1.6403x; 1.6403x over previous
#include <cuda_runtime.h>
#include <cuda_bf16.h>
#include <math.h>

// Shapes
#define B_SZ 4096
#define P_SZ 256
#define F_SZ 20
#define H_SZ 18
#define W_SZ 18
#define HW   (H_SZ * W_SZ)          // 324
#define FHW  (F_SZ * HW)            // 6480
#define PI_C 3.14159f

// Scratch (no allocations allowed; use device globals)
__device__ float g_h[B_SZ * P_SZ];          // relu(pc @ W1 + b1)
__device__ float g_aff[B_SZ * F_SZ * 4];    // per (b,f): u, v, Bx, By

// ---------------------------------------------------------------------------
// Kernel 1: h = relu(pc @ W1 + b1).  M=4096, N=256, K=256.
// 64x64 tile, BK=16, 256 threads, 4x4 per thread -> 256 CTAs (better than the
// previous 128-CTA single partial wave).
// ---------------------------------------------------------------------------
__global__ void __launch_bounds__(256) gemm_relu_kernel(
    const float* __restrict__ A,      // (4096, 256)
    const float* __restrict__ W,      // (256, 256)
    const float* __restrict__ bias)   // (256)
{
    const int BM = 64, BN = 64, BK = 16;
    __shared__ float As[BK][BM + 4];  // [k][m]
    __shared__ float Bs[BK][BN];      // [k][n]

    int tid = threadIdx.x;
    int tx = tid & 15;      // 0..15 -> col groups of 4
    int ty = tid >> 4;      // 0..15 -> row groups of 4
    int row0 = blockIdx.x * BM;
    int col0 = blockIdx.y * BN;

    float acc[4][4];
#pragma unroll
    for (int i = 0; i < 4; i++)
#pragma unroll
        for (int j = 0; j < 4; j++) acc[i][j] = 0.f;

    for (int k0 = 0; k0 < P_SZ; k0 += BK) {
        // A tile: 64x16 -> transposed As[k][m]; 256 float4, 1/thread
        {
            int m  = tid >> 2;            // 0..63
            int kq = (tid & 3) << 2;      // 0,4,8,12
            float4 v = *(const float4*)&A[(row0 + m) * P_SZ + k0 + kq];
            As[kq + 0][m] = v.x;
            As[kq + 1][m] = v.y;
            As[kq + 2][m] = v.z;
            As[kq + 3][m] = v.w;
        }
        // B tile: 16x64; 256 float4, 1/thread
        {
            int k = tid >> 4;             // 0..15
            int n = (tid & 15) << 2;      // 0..60
            *(float4*)&Bs[k][n] = *(const float4*)&W[(k0 + k) * P_SZ + col0 + n];
        }
        __syncthreads();

#pragma unroll
        for (int k = 0; k < BK; k++) {
            float4 av = *(const float4*)&As[k][ty * 4];
            float4 bv = *(const float4*)&Bs[k][tx * 4];
            float a[4] = {av.x, av.y, av.z, av.w};
            float b[4] = {bv.x, bv.y, bv.z, bv.w};
#pragma unroll
            for (int i = 0; i < 4; i++)
#pragma unroll
                for (int j = 0; j < 4; j++)
                    acc[i][j] = fmaf(a[i], b[j], acc[i][j]);
        }
        __syncthreads();
    }

    // Epilogue: + bias, relu, float4 stores
    int c = col0 + tx * 4;
    float4 bb = *(const float4*)&bias[c];
#pragma unroll
    for (int i = 0; i < 4; i++) {
        int r = row0 + ty * 4 + i;
        float4 v;
        v.x = fmaxf(acc[i][0] + bb.x, 0.f);
        v.y = fmaxf(acc[i][1] + bb.y, 0.f);
        v.z = fmaxf(acc[i][2] + bb.z, 0.f);
        v.w = fmaxf(acc[i][3] + bb.w, 0.f);
        *(float4*)&g_h[r * P_SZ + c] = v;
    }
}

// ---------------------------------------------------------------------------
// Kernel 2: raw = h @ [Ws|Wr|Wt] (4096x80 GEMM, K=256) + activations.
// Proper tiled GEMM: BM=32, BN=80, BK=32; weights staged in SMEM per k-tile
// (no more per-thread strided global k-loops).
// ---------------------------------------------------------------------------
__global__ void __launch_bounds__(256) params_kernel(
    const float* __restrict__ Ws, const float* __restrict__ bs,
    const float* __restrict__ Wr, const float* __restrict__ br,
    const float* __restrict__ Wt, const float* __restrict__ bt)
{
    __shared__ float hs[32][33];      // [m][k]
    __shared__ float ws[32][80];      // [k][j]
    __shared__ float raw[32][80];

    int tid = threadIdx.x;
    int b0 = blockIdx.x * 32;
    int ty = tid >> 3;                // 0..31 (row)
    int tx = tid & 7;                 // 0..7  (col group of 10)

    float acc[10];
#pragma unroll
    for (int j = 0; j < 10; j++) acc[j] = 0.f;

    for (int k0 = 0; k0 < P_SZ; k0 += 32) {
        // h tile: 32x32, float4 per thread
        {
            int m  = tid >> 3;            // 0..31
            int kq = (tid & 7) << 2;      // 0..28
            float4 v = *(const float4*)&g_h[(b0 + m) * P_SZ + k0 + kq];
            hs[m][kq + 0] = v.x;
            hs[m][kq + 1] = v.y;
            hs[m][kq + 2] = v.z;
            hs[m][kq + 3] = v.w;
        }
        // W tile: 32x80 (2560 scalars, 10/thread)
        for (int i = tid; i < 32 * 80; i += 256) {
            int k = i / 80;
            int j = i - k * 80;
            int kk = k0 + k;
            float w;
            if (j < 20)       w = Ws[kk * 20 + j];
            else if (j < 40)  w = Wr[kk * 20 + (j - 20)];
            else              w = Wt[kk * 40 + (j - 40)];
            ws[k][j] = w;
        }
        __syncthreads();

#pragma unroll
        for (int k = 0; k < 32; k++) {
            float a = hs[ty][k];
#pragma unroll
            for (int j = 0; j < 10; j++)
                acc[j] = fmaf(a, ws[k][tx * 10 + j], acc[j]);
        }
        __syncthreads();
    }

#pragma unroll
    for (int j = 0; j < 10; j++) raw[ty][tx * 10 + j] = acc[j];
    __syncthreads();

    // Activations: 32 rows x 20 channels
    for (int o = tid; o < 32 * F_SZ; o += 256) {
        int bi = o / F_SZ, f = o - bi * F_SZ;
        float scale = 2.f / (1.f + expf(-(raw[bi][f] + bs[f])));
        float angle = tanhf(raw[bi][20 + f] + br[f]) * PI_C;
        float txn = tanhf(raw[bi][40 + 2 * f] + bt[2 * f]);
        float tyn = tanhf(raw[bi][41 + 2 * f] + bt[2 * f + 1]);
        float s, c;
        sincosf(angle, &s, &c);
        float4 r = make_float4(9.f * scale * c,
                               9.f * scale * s,
                               9.f * txn + 8.5f,
                               9.f * tyn + 8.5f);
        *(float4*)&g_aff[(b0 + bi) * 80 + f * 4] = r;
    }
}

// ---------------------------------------------------------------------------
// Kernel 3: trilinear sampling. One CTA per batch; 352 threads; thread = one
// (y,x) pixel; fully-unrolled f loop so z-interp constants fold per channel.
// ---------------------------------------------------------------------------
__global__ void __launch_bounds__(352) sample_kernel(
    const float* __restrict__ fmap,   // (B, 20, 18, 18)
    float* __restrict__ out)          // (B, 20, 18, 18)
{
    __shared__ float vol[FHW];
    __shared__ float4 affs[F_SZ];
    int b = blockIdx.x;
    int tid = threadIdx.x;

    const float4* fb4 = (const float4*)(fmap + b * FHW);
    float4* vol4 = (float4*)vol;
    for (int i = tid; i < FHW / 4; i += 352) vol4[i] = fb4[i];
    if (tid < F_SZ) affs[tid] = *(const float4*)&g_aff[b * 80 + tid * 4];
    __syncthreads();

    if (tid >= HW) return;
    int y = tid / W_SZ;
    int x = tid - y * W_SZ;
    float gx = (2.f / 17.f) * x - 1.f;
    float gy = (2.f / 17.f) * y - 1.f;
    float* ob = out + b * FHW + tid;

#pragma unroll
    for (int f = 0; f < F_SZ; f++) {
        // z interp: pure function of f -> constant-folds under full unroll
        float iz = f * (20.f / 19.f) - 0.5f;
        float z0f = floorf(iz);
        int z0 = (int)z0f;
        float wz = iz - z0f;
        const bool has0 = (f > 0);          // z0 >= 0  (f=0 -> z0=-1)
        const bool has1 = (f < F_SZ - 1);   // z0+1 <= 19 (f=19 -> z0=19)
        float w0 = has0 ? (1.f - wz) : 0.f;
        float w1 = has1 ? wz : 0.f;
        const float* p0 = vol + (has0 ? z0 : 0) * HW;
        const float* p1 = vol + (has1 ? z0 + 1 : F_SZ - 1) * HW;

        float4 A = affs[f];
        float ix = A.x * gx - A.y * gy + A.z;
        float iy = A.y * gx + A.x * gy + A.w;

        float x0f = floorf(ix), y0f = floorf(iy);
        float wx = ix - x0f, wy = iy - y0f;
        int x0 = (int)x0f, y0 = (int)y0f;

        float res = 0.f;
#pragma unroll
        for (int cy = 0; cy < 2; cy++) {
            int yy = y0 + cy;
            if ((unsigned)yy >= (unsigned)H_SZ) continue;
            float wyy = cy ? wy : 1.f - wy;
            int base = yy * W_SZ;
#pragma unroll
            for (int cx = 0; cx < 2; cx++) {
                int xx = x0 + cx;
                if ((unsigned)xx >= (unsigned)W_SZ) continue;
                float wxx = cx ? wx : 1.f - wx;
                int id = base + xx;
                float v0 = has0 ? p0[id] : 0.f;   // dead-load eliminated when folded
                float v1 = has1 ? p1[id] : 0.f;
                float v = w0 * v0 + w1 * v1;
                res = fmaf(wxx * wyy, v, res);
            }
        }
        ob[f * HW] = res;
    }
}

// ---------------------------------------------------------------------------
extern "C" void kernel_launch(void* const* d_in, const int* in_sizes, int n_in,
                              void* d_out, int out_size)
{
    const float* fmap = (const float*)d_in[0];  // (4096, 20, 18, 18)
    const float* pc   = (const float*)d_in[1];  // (4096, 256)
    const float* W1   = (const float*)d_in[2];  // (256, 256)
    const float* b1   = (const float*)d_in[3];  // (256)
    const float* Ws   = (const float*)d_in[4];  // (256, 20)
    const float* bs   = (const float*)d_in[5];  // (20)
    const float* Wr   = (const float*)d_in[6];  // (256, 20)
    const float* br   = (const float*)d_in[7];  // (20)
    const float* Wt   = (const float*)d_in[8];  // (256, 40)
    const float* bt   = (const float*)d_in[9];  // (40)
    float* out = (float*)d_out;

    gemm_relu_kernel<<<dim3(B_SZ / 64, P_SZ / 64), 256>>>(pc, W1, b1);
    params_kernel<<<B_SZ / 32, 256>>>(Ws, bs, Wr, br, Wt, bt);
    sample_kernel<<<B_SZ, 352>>>(fmap, out);
}